// round 7
// baseline (speedup 1.0000x reference)
#include <cuda_runtime.h>
#include <math.h>

#define BB 128
#define HH 64
#define WW 64
#define AA 9
#define NN (HH*WW*AA)           // 36864 predictions per image
#define KK 100
#define NBUCK 2048
#define CAP 1024                // candidate capacity per image
#define SPLIT 9                 // collect CTAs per image
#define NSEG (NN/SPLIT)         // 4096 records per collect CTA
#define NF4SEG (NSEG*5/4)       // 5120 float4s per collect CTA
#define THREADS 256
#define ITERS (NF4SEG/THREADS)  // 20 float4 loads per thread
#define DS_ 1024.0f
#define STRIDE_ 64.0f
#define EPS_ 1e-7f
#define T0_ 1.25f               // static logit collect-threshold (fallback-guarded)

// globals (zero-initialized at load; kernel self-resets for graph replay)
__device__ unsigned long long g_cand[BB][CAP];
__device__ int g_cnt[BB];
__device__ unsigned g_segdone[BB];
__device__ float g_scratch[BB * 4];
__device__ unsigned g_done;

__device__ __forceinline__ unsigned fkey(float x) {
    unsigned u = __float_as_uint(x);
    return (u & 0x80000000u) ? ~u : (u | 0x80000000u);
}

__device__ __forceinline__ unsigned long long make_cand(float x, int e) {
    float conf = 1.0f / (1.0f + __expf(-x));           // conf in (0,1)
    unsigned ck = __float_as_uint(conf) ^ 0x80000000u; // order-preserving (conf>0)
    return ((unsigned long long)ck << 32) | (unsigned)(0xFFFFFFFFu - (unsigned)e);
}

__global__ __launch_bounds__(THREADS)
void fused_kernel(const float* __restrict__ out5,
                  const float* __restrict__ tboxes,
                  const float* __restrict__ anchors,
                  float* __restrict__ out)
{
    __shared__ union {
        unsigned hist[NBUCK];                  // fallback only (8KB)
        unsigned long long cand[CAP];          // 8KB
    } u;
    __shared__ unsigned s_part[THREADS];
    __shared__ float s_bx1[KK], s_by1[KK], s_bx2[KK], s_by2[KK], s_ba[KK], s_val[KK];
    __shared__ float s_tx1[KK], s_ty1[KK], s_tx2[KK], s_ty2[KK];
    __shared__ unsigned long long s_best[KK];
    __shared__ unsigned s_sup[KK][4];
    __shared__ unsigned s_kw[4];
    __shared__ int s_cnt, s_bsel, s_go, s_last;
    __shared__ float s_anc[AA * 2];
    __shared__ float s_red[3][THREADS / 32];

    const int tid = threadIdx.x;
    const int img = blockIdx.x / SPLIT;
    const int seg = blockIdx.x % SPLIT;
    const float* __restrict__ ip = out5 + (size_t)img * NN * 5;

    // ========== phase 1: coalesced float4 conf stream (all CTAs) ==========
    // float4 j of an image: j%5==1 -> conf in .x (record (4j+0)/5)
    //                        j%5==2 -> .y, 3 -> .z, 4 -> .w;  j%5==0: none
    {
        const float4* __restrict__ ip4 = (const float4*)ip;   // 46080 f4/image
        const int base = seg * NF4SEG;
        #pragma unroll 4
        for (int k = 0; k < ITERS; k++) {
            int j = base + tid + k * THREADS;
            float4 v = __ldg(&ip4[j]);
            int r = j % 5;
            if (r != 0) {
                float x = (r == 1) ? v.x : (r == 2) ? v.y : (r == 3) ? v.z : v.w;
                if (x > T0_) {
                    int e = (4 * j + (r - 1)) / 5;            // record index in image
                    int q = atomicAdd(&g_cnt[img], 1);
                    if (q < CAP) g_cand[img][q] = make_cand(x, e);
                }
            }
        }
    }
    __threadfence();                 // each thread fences its own candidate stores
    __syncthreads();
    if (tid == 0) {
        unsigned q = atomicAdd(&g_segdone[img], 1u);
        s_go = (q == SPLIT - 1) ? 1 : 0;
    }
    __syncthreads();
    if (!s_go) return;               // non-last CTAs exit; last runs the tail

    // ================= phase 2: per-image tail (1 CTA per image) ==============
    if (tid == 0) g_segdone[img] = 0;            // reset for next graph replay
    __threadfence();                             // acquire candidates from peers

    if (tid < AA * 2) s_anc[tid] = anchors[tid];
    if (tid == 0) { s_kw[0] = s_kw[1] = s_kw[2] = s_kw[3] = 0; }
    for (int i = tid; i < KK * 4; i += THREADS) ((unsigned*)s_sup)[i] = 0;
    if (tid < KK) s_best[tid] = 0ull;

    const int gcnt = g_cnt[img];
    if (tid == 0) s_cnt = gcnt;
    {
        int C0 = min(gcnt, CAP);
        for (int i = tid; i < C0; i += THREADS) u.cand[i] = g_cand[img][i];
    }
    __syncthreads();

    // ---- fallback: exact histogram top-K (never taken for typical inputs) ----
    if (gcnt < KK || gcnt > CAP) {
        for (int i = tid; i < NBUCK; i += THREADS) u.hist[i] = 0;
        if (tid == 0) s_cnt = 0;
        __syncthreads();
        for (int e = tid; e < NN; e += THREADS) {
            float x = ip[(size_t)e * 5 + 4];
            atomicAdd(&u.hist[fkey(x) >> 21], 1u);
        }
        __syncthreads();
        {
            unsigned s = 0;
            int base = tid * (NBUCK / THREADS);
            #pragma unroll
            for (int j = 0; j < NBUCK / THREADS; j++) s += u.hist[base + j];
            s_part[tid] = s;
        }
        __syncthreads();
        if (tid == 0) {
            unsigned cum = 0; int sg = 0;
            for (int t = THREADS - 1; t >= 0; t--) {
                if (cum + s_part[t] >= KK) { sg = t; break; }
                cum += s_part[t];
            }
            int bsel = sg * (NBUCK / THREADS);
            for (int b = sg * (NBUCK / THREADS) + (NBUCK / THREADS) - 1;
                 b >= sg * (NBUCK / THREADS); b--) {
                cum += u.hist[b];
                if (cum >= KK) { bsel = b; break; }
            }
            s_bsel = bsel;
        }
        __syncthreads();
        const int bsel = s_bsel;
        for (int e = tid; e < NN; e += THREADS) {
            float x = ip[(size_t)e * 5 + 4];
            if ((int)(fkey(x) >> 21) >= bsel) {
                int pos = atomicAdd(&s_cnt, 1);
                if (pos < CAP) u.cand[pos] = make_cand(x, e);
            }
        }
        __syncthreads();
    }

    int C = min(s_cnt, CAP);
    int P = 128;
    while (P < C) P <<= 1;
    if (P > CAP) P = CAP;
    for (int i = C + tid; i < P; i += THREADS) u.cand[i] = 0ull;
    __syncthreads();

    // ---- bitonic sort descending (conf desc, index asc) ----
    for (int k = 2; k <= P; k <<= 1) {
        for (int j = k >> 1; j > 0; j >>= 1) {
            for (int i = tid; i < P; i += THREADS) {
                int ixj = i ^ j;
                if (ixj > i) {
                    unsigned long long va = u.cand[i], vb = u.cand[ixj];
                    bool desc = ((i & k) == 0);
                    if ((va < vb) == desc) { u.cand[i] = vb; u.cand[ixj] = va; }
                }
            }
            __syncthreads();
        }
    }

    // ---- build top-K boxes (clip + fix), cmask, targets ----
    if (tid < KK) {
        unsigned long long v = u.cand[tid];
        unsigned ck = (unsigned)(v >> 32);
        float conf = __uint_as_float(ck ^ 0x80000000u);
        int e = (int)(0xFFFFFFFFu - (unsigned)(v & 0xFFFFFFFFull));
        float o0 = ip[(size_t)e * 5 + 0], o1 = ip[(size_t)e * 5 + 1];
        float o2 = ip[(size_t)e * 5 + 2], o3 = ip[(size_t)e * 5 + 3];
        int a = e % AA;
        int w = (e / AA) % WW;
        int h = e / (AA * WW);
        float px = (1.0f / (1.0f + __expf(-o0)) + (float)w) * STRIDE_;
        float py = (1.0f / (1.0f + __expf(-o1)) + (float)h) * STRIDE_;
        float pw = __expf(o2) * s_anc[a * 2 + 0] * DS_;
        float ph = __expf(o3) * s_anc[a * 2 + 1] * DS_;
        float c0 = px - pw * 0.5f, c1 = py - ph * 0.5f;
        float c2 = px + pw * 0.5f, c3 = py + ph * 0.5f;
        c0 = fminf(fmaxf(c0, 0.0f), DS_); c1 = fminf(fmaxf(c1, 0.0f), DS_);
        c2 = fminf(fmaxf(c2, 0.0f), DS_); c3 = fminf(fmaxf(c3, 0.0f), DS_);
        float x1 = fminf(c0, c2), x2 = fmaxf(c0, c2);
        float y1 = fminf(c1, c3), y2 = fmaxf(c1, c3);
        if (x1 == x2) x2 = x1 + 1.0f;
        if (y1 == y2) y2 = y1 + 1.0f;
        s_bx1[tid] = x1; s_by1[tid] = y1; s_bx2[tid] = x2; s_by2[tid] = y2;
        s_ba[tid] = (x2 - x1) * (y2 - y1);
        s_val[tid] = conf;
        if (conf >= 0.5f) atomicOr(&s_kw[tid >> 5], 1u << (tid & 31));

        const float* tp = tboxes + ((size_t)img * KK + tid) * 4;
        float t0 = fminf(fmaxf(tp[0], 0.0f), DS_);
        float t1 = fminf(fmaxf(tp[1], 0.0f), DS_);
        float t2 = fminf(fmaxf(tp[2], 0.0f), DS_);
        float t3 = fminf(fmaxf(tp[3], 0.0f), DS_);
        float tx1 = fminf(t0, t2), tx2 = fmaxf(t0, t2);
        float ty1 = fminf(t1, t3), ty2 = fmaxf(t1, t3);
        if (tx1 == tx2) tx2 = tx1 + 1.0f;
        if (ty1 == ty2) ty2 = ty1 + 1.0f;
        s_tx1[tid] = tx1; s_ty1[tid] = ty1; s_tx2[tid] = tx2; s_ty2[tid] = ty2;
    }
    __syncthreads();

    // ---- pairwise pred-pred suppression bitmask (parallel, fast div) ----
    for (int p = tid; p < KK * KK; p += THREADS) {
        int i = p / KK, j = p % KK;
        if (j > i) {
            float lx = fmaxf(s_bx1[i], s_bx1[j]);
            float ly = fmaxf(s_by1[i], s_by1[j]);
            float rx = fminf(s_bx2[i], s_bx2[j]);
            float ry = fminf(s_by2[i], s_by2[j]);
            float iw = fmaxf(rx - lx, 0.0f), ih = fmaxf(ry - ly, 0.0f);
            float inter = iw * ih;
            float iou = __fdividef(inter, s_ba[i] + s_ba[j] - inter + EPS_);
            if (iou > 0.5f) atomicOr(&s_sup[i][j >> 5], 1u << (j & 31));
        }
    }
    __syncthreads();

    // ---- greedy NMS sweep (exact reference semantics), serial in thread 0 ----
    if (tid == 0) {
        const uint4* supv = (const uint4*)s_sup;
        unsigned kw0 = s_kw[0], kw1 = s_kw[1], kw2 = s_kw[2], kw3 = s_kw[3];
        #pragma unroll 4
        for (int i = 0; i < KK; i++) {
            uint4 r = supv[i];
            unsigned wv = (i < 32) ? kw0 : (i < 64) ? kw1 : (i < 96) ? kw2 : kw3;
            if ((wv >> (i & 31)) & 1u) {
                kw0 &= ~r.x; kw1 &= ~r.y; kw2 &= ~r.z; kw3 &= ~r.w;
            }
        }
        s_kw[0] = kw0; s_kw[1] = kw1; s_kw[2] = kw2; s_kw[3] = kw3;
    }
    __syncthreads();

    // ---- per-target max-IoU argmax: all 256 threads over 10000 pairs ----
    {
        unsigned kw[4] = { s_kw[0], s_kw[1], s_kw[2], s_kw[3] };
        for (int q = tid; q < KK * KK; q += THREADS) {
            int t = q / KK, p = q % KK;
            float kf = ((kw[p >> 5] >> (p & 31)) & 1u) ? 1.0f : 0.0f;
            float lx = fmaxf(s_bx1[p], s_tx1[t]);
            float ly = fmaxf(s_by1[p], s_ty1[t]);
            float rx = fminf(s_bx2[p], s_tx2[t]);
            float ry = fminf(s_by2[p], s_ty2[t]);
            float iw = fmaxf(rx - lx, 0.0f), ih = fmaxf(ry - ly, 0.0f);
            float inter = iw * ih;
            float ta = (s_tx2[t] - s_tx1[t]) * (s_ty2[t] - s_ty1[t]);
            float iou = __fdividef(inter, s_ba[p] + ta - inter + EPS_);
            float v = iou * kf;                  // v >= 0 -> bits monotonic
            unsigned long long key = ((unsigned long long)__float_as_uint(v) << 32)
                                   | (unsigned)(0xFFFFFFFFu - (unsigned)p);
            atomicMax(&s_best[t], key);
        }
    }
    __syncthreads();

    // ---- per-target DIoU + penalty terms ----
    float diou = 0.0f, lowv = 0.0f, highv = 0.0f;
    if (tid < KK) {
        unsigned long long key = s_best[tid];
        float max_iou = fmaxf(__uint_as_float((unsigned)(key >> 32)), 0.0f);
        int best = (int)(0xFFFFFFFFu - (unsigned)(key & 0xFFFFFFFFull));
        float tx1 = s_tx1[tid], ty1 = s_ty1[tid], tx2 = s_tx2[tid], ty2 = s_ty2[tid];
        float pbx1 = s_bx1[best], pby1 = s_by1[best];
        float pbx2 = s_bx2[best], pby2 = s_by2[best];
        float pcx = (pbx1 + pbx2) * 0.5f, pcy = (pby1 + pby2) * 0.5f;
        float tcx = (tx1 + tx2) * 0.5f,  tcy = (ty1 + ty2) * 0.5f;
        float cd = (pcx - tcx) * (pcx - tcx) + (pcy - tcy) * (pcy - tcy);
        float ex1 = fminf(pbx1, tx1), ey1 = fminf(pby1, ty1);
        float ex2 = fmaxf(pbx2, tx2), ey2 = fmaxf(pby2, ty2);
        float dg = (ex2 - ex1) * (ex2 - ex1) + (ey2 - ey1) * (ey2 - ey1);
        diou = 1.0f - (max_iou - __fdividef(cd, dg + EPS_));

        float kfr = ((s_kw[tid >> 5] >> (tid & 31)) & 1u) ? 1.0f : 0.0f;
        float val = s_val[tid];
        lowv  = fmaxf(-val, 0.0f) * kfr;
        highv = fmaxf(val - 1.0f, 0.0f) * kfr;
    }

    // deterministic reduction: warp shuffles + fixed-order smem combine
    #pragma unroll
    for (int off = 16; off; off >>= 1) {
        diou  += __shfl_down_sync(0xFFFFFFFFu, diou,  off);
        lowv  += __shfl_down_sync(0xFFFFFFFFu, lowv,  off);
        highv += __shfl_down_sync(0xFFFFFFFFu, highv, off);
    }
    if ((tid & 31) == 0) {
        s_red[0][tid >> 5] = diou;
        s_red[1][tid >> 5] = lowv;
        s_red[2][tid >> 5] = highv;
    }
    __syncthreads();
    if (tid == 0) {
        float d = 0.0f, l = 0.0f, h = 0.0f;
        #pragma unroll
        for (int w = 0; w < THREADS / 32; w++) {
            d += s_red[0][w]; l += s_red[1][w]; h += s_red[2][w];
        }
        float cnt = (float)(__popc(s_kw[0]) + __popc(s_kw[1]) +
                            __popc(s_kw[2]) + __popc(s_kw[3]));
        g_scratch[img * 4 + 0] = d;
        g_scratch[img * 4 + 1] = l;
        g_scratch[img * 4 + 2] = h;
        g_scratch[img * 4 + 3] = cnt;
        g_cnt[img] = 0;                 // reset for next graph replay
        __threadfence();
        unsigned t = atomicAdd(&g_done, 1u);
        s_last = (t == BB - 1) ? 1 : 0;
    }
    __syncthreads();

    // ---- last image's tail CTA performs the global finalize ----
    if (s_last) {
        __threadfence();
        float d = 0.0f, l = 0.0f, h = 0.0f, c = 0.0f;
        if (tid < BB) {
            d = g_scratch[tid * 4 + 0];
            l = g_scratch[tid * 4 + 1];
            h = g_scratch[tid * 4 + 2];
            c = g_scratch[tid * 4 + 3];
        }
        #pragma unroll
        for (int off = 16; off; off >>= 1) {
            d += __shfl_down_sync(0xFFFFFFFFu, d, off);
            l += __shfl_down_sync(0xFFFFFFFFu, l, off);
            h += __shfl_down_sync(0xFFFFFFFFu, h, off);
            c += __shfl_down_sync(0xFFFFFFFFu, c, off);
        }
        if ((tid & 31) == 0) {
            s_red[0][tid >> 5] = d;
            s_red[1][tid >> 5] = l;
            s_red[2][tid >> 5] = h;
            s_part[tid >> 5]   = __float_as_uint(c);
        }
        __syncthreads();
        if (tid == 0) {
            float D = 0.0f, L = 0.0f, H = 0.0f, Cn = 0.0f;
            #pragma unroll
            for (int w = 0; w < THREADS / 32; w++) {
                D += s_red[0][w]; L += s_red[1][w]; H += s_red[2][w];
                Cn += __uint_as_float(s_part[w]);
            }
            float n = fmaxf(Cn, 1.0f);
            out[0] = D / (float)(BB * KK) + L / n + 0.5f * (H / n);
            g_done = 0;                 // reset for next graph replay
        }
    }
}

extern "C" void kernel_launch(void* const* d_in, const int* in_sizes, int n_in,
                              void* d_out, int out_size)
{
    const float* output  = (const float*)d_in[0];   // (128,64,64,9,5) fp32
    const float* tboxes  = (const float*)d_in[1];   // (128,100,4) fp32
    const float* anchors = (const float*)d_in[2];   // (9,2) fp32
    float* out = (float*)d_out;

    fused_kernel<<<BB * SPLIT, THREADS>>>(output, tboxes, anchors, out);
}

// round 9
// speedup vs baseline: 1.2281x; 1.2281x over previous
#include <cuda_runtime.h>
#include <math.h>

#define BB 128
#define HH 64
#define WW 64
#define AA 9
#define NN (HH*WW*AA)           // 36864 predictions per image
#define KK 100
#define NBUCK 2048
#define CAP 1024                // candidate capacity per image
#define SPLIT 6                 // collect CTAs per image
#define NSEG (NN/SPLIT)         // 6144 records per collect CTA
#define THREADS 512
#define DS_ 1024.0f
#define STRIDE_ 64.0f
#define EPS_ 1e-7f
#define T0_ 1.25f               // static logit collect-threshold (fallback-guarded)

// globals (zero-initialized at load; kernel self-resets for graph replay)
__device__ unsigned long long g_cand[BB][CAP];
__device__ int g_cnt[BB];
__device__ unsigned g_segdone[BB];
__device__ float g_scratch[BB * 4];
__device__ unsigned g_done;

__device__ __forceinline__ unsigned fkey(float x) {
    unsigned u = __float_as_uint(x);
    return (u & 0x80000000u) ? ~u : (u | 0x80000000u);
}

__device__ __forceinline__ unsigned long long make_cand(float x, int e) {
    float conf = 1.0f / (1.0f + __expf(-x));           // conf in (0,1)
    unsigned ck = __float_as_uint(conf) ^ 0x80000000u; // order-preserving (conf>0)
    return ((unsigned long long)ck << 32) | (unsigned)(0xFFFFFFFFu - (unsigned)e);
}

__global__ __launch_bounds__(THREADS)
void fused_kernel(const float* __restrict__ out5,
                  const float* __restrict__ tboxes,
                  const float* __restrict__ anchors,
                  float* __restrict__ out)
{
    __shared__ union {
        unsigned hist[NBUCK];                  // fallback only (8KB)
        unsigned long long cand[CAP];          // 8KB
    } u;
    __shared__ unsigned s_part[THREADS];
    __shared__ int s_sele[KK];
    __shared__ float s_selc[KK];
    __shared__ float s_bx1[KK], s_by1[KK], s_bx2[KK], s_by2[KK], s_ba[KK], s_val[KK];
    __shared__ float s_tx1[KK], s_ty1[KK], s_tx2[KK], s_ty2[KK];
    __shared__ unsigned long long s_best[KK];
    __shared__ unsigned s_sup[KK][4];
    __shared__ unsigned s_kw[4];
    __shared__ int s_cnt, s_bsel, s_go, s_last;
    __shared__ float s_anc[AA * 2];
    __shared__ float s_red[3][THREADS / 32];

    const int tid = threadIdx.x;
    const int img = blockIdx.x / SPLIT;
    const int seg = blockIdx.x % SPLIT;
    const float* __restrict__ ip = out5 + (size_t)img * NN * 5;

    // ========== phase 1: conf stream (all CTAs), scalar loads (R6-proven) ====
    {
        const int base = seg * NSEG;
        #pragma unroll 4
        for (int i = tid; i < NSEG; i += THREADS) {
            int e = base + i;
            float x = __ldg(&ip[(size_t)e * 5 + 4]);
            if (x > T0_) {
                int q = atomicAdd(&g_cnt[img], 1);
                if (q < CAP) g_cand[img][q] = make_cand(x, e);
            }
        }
    }
    __threadfence();
    __syncthreads();
    if (tid == 0) {
        unsigned q = atomicAdd(&g_segdone[img], 1u);
        s_go = (q == SPLIT - 1) ? 1 : 0;
    }
    __syncthreads();
    if (!s_go) return;               // non-last CTAs exit; last runs the tail

    // ================= phase 2: per-image tail (1 CTA per image) ==============
    if (tid == 0) g_segdone[img] = 0;            // reset for next graph replay
    __threadfence();                             // acquire candidates from peers

    if (tid < AA * 2) s_anc[tid] = anchors[tid];
    if (tid == 0) { s_kw[0] = s_kw[1] = s_kw[2] = s_kw[3] = 0; }
    for (int i = tid; i < KK * 4; i += THREADS) ((unsigned*)s_sup)[i] = 0;
    if (tid < KK) s_best[tid] = 0ull;

    const int gcnt = g_cnt[img];
    if (tid == 0) s_cnt = gcnt;
    {
        int C0 = min(gcnt, CAP);
        for (int i = tid; i < C0; i += THREADS) u.cand[i] = g_cand[img][i];
    }
    __syncthreads();

    // ---- fallback: exact histogram top-K (never taken for typical inputs) ----
    if (gcnt < KK || gcnt > CAP) {
        for (int i = tid; i < NBUCK; i += THREADS) u.hist[i] = 0;
        if (tid == 0) s_cnt = 0;
        __syncthreads();
        for (int e = tid; e < NN; e += THREADS) {
            float x = ip[(size_t)e * 5 + 4];
            atomicAdd(&u.hist[fkey(x) >> 21], 1u);
        }
        __syncthreads();
        {
            unsigned s = 0;
            int base = tid * (NBUCK / THREADS);
            #pragma unroll
            for (int j = 0; j < NBUCK / THREADS; j++) s += u.hist[base + j];
            s_part[tid] = s;
        }
        __syncthreads();
        if (tid == 0) {
            unsigned cum = 0; int sg = 0;
            for (int t = THREADS - 1; t >= 0; t--) {
                if (cum + s_part[t] >= KK) { sg = t; break; }
                cum += s_part[t];
            }
            int bsel = sg * (NBUCK / THREADS);
            for (int b = sg * (NBUCK / THREADS) + (NBUCK / THREADS) - 1;
                 b >= sg * (NBUCK / THREADS); b--) {
                cum += u.hist[b];
                if (cum >= KK) { bsel = b; break; }
            }
            s_bsel = bsel;
        }
        __syncthreads();
        const int bsel = s_bsel;
        for (int e = tid; e < NN; e += THREADS) {
            float x = ip[(size_t)e * 5 + 4];
            if ((int)(fkey(x) >> 21) >= bsel) {
                int pos = atomicAdd(&s_cnt, 1);
                if (pos < CAP) u.cand[pos] = make_cand(x, e);
            }
        }
        __syncthreads();
    }

    const int C = min(s_cnt, CAP);

    // ---- rank selection: exact top-K without sort (keys unique) ----
    // rank(c) = #{j : key_j > key_c}; rank < KK -> slot rank
    for (int c = tid; c < C; c += THREADS) {
        unsigned long long key = u.cand[c];
        int rank = 0;
        #pragma unroll 4
        for (int j = 0; j < C; j++) rank += (u.cand[j] > key) ? 1 : 0;
        if (rank < KK) {
            s_sele[rank] = (int)(0xFFFFFFFFu - (unsigned)(key & 0xFFFFFFFFull));
            s_selc[rank] = __uint_as_float((unsigned)(key >> 32) ^ 0x80000000u);
        }
    }
    __syncthreads();

    // ---- build top-K boxes (clip + fix), cmask, targets ----
    if (tid < KK) {
        int e = s_sele[tid];
        float conf = s_selc[tid];
        float o0 = ip[(size_t)e * 5 + 0], o1 = ip[(size_t)e * 5 + 1];
        float o2 = ip[(size_t)e * 5 + 2], o3 = ip[(size_t)e * 5 + 3];
        int a = e % AA;
        int w = (e / AA) % WW;
        int h = e / (AA * WW);
        float px = (1.0f / (1.0f + __expf(-o0)) + (float)w) * STRIDE_;
        float py = (1.0f / (1.0f + __expf(-o1)) + (float)h) * STRIDE_;
        float pw = __expf(o2) * s_anc[a * 2 + 0] * DS_;
        float ph = __expf(o3) * s_anc[a * 2 + 1] * DS_;
        float c0 = px - pw * 0.5f, c1 = py - ph * 0.5f;
        float c2 = px + pw * 0.5f, c3 = py + ph * 0.5f;
        c0 = fminf(fmaxf(c0, 0.0f), DS_); c1 = fminf(fmaxf(c1, 0.0f), DS_);
        c2 = fminf(fmaxf(c2, 0.0f), DS_); c3 = fminf(fmaxf(c3, 0.0f), DS_);
        float x1 = fminf(c0, c2), x2 = fmaxf(c0, c2);
        float y1 = fminf(c1, c3), y2 = fmaxf(c1, c3);
        if (x1 == x2) x2 = x1 + 1.0f;
        if (y1 == y2) y2 = y1 + 1.0f;
        s_bx1[tid] = x1; s_by1[tid] = y1; s_bx2[tid] = x2; s_by2[tid] = y2;
        s_ba[tid] = (x2 - x1) * (y2 - y1);
        s_val[tid] = conf;
        if (conf >= 0.5f) atomicOr(&s_kw[tid >> 5], 1u << (tid & 31));

        const float* tp = tboxes + ((size_t)img * KK + tid) * 4;
        float t0 = fminf(fmaxf(tp[0], 0.0f), DS_);
        float t1 = fminf(fmaxf(tp[1], 0.0f), DS_);
        float t2 = fminf(fmaxf(tp[2], 0.0f), DS_);
        float t3 = fminf(fmaxf(tp[3], 0.0f), DS_);
        float tx1 = fminf(t0, t2), tx2 = fmaxf(t0, t2);
        float ty1 = fminf(t1, t3), ty2 = fmaxf(t1, t3);
        if (tx1 == tx2) tx2 = tx1 + 1.0f;
        if (ty1 == ty2) ty2 = ty1 + 1.0f;
        s_tx1[tid] = tx1; s_ty1[tid] = ty1; s_tx2[tid] = tx2; s_ty2[tid] = ty2;
    }
    __syncthreads();

    // ---- pairwise pred-pred suppression bitmask ----
    // i = q % KK (lane-varying -> conflict-free atomicOr), j = q / KK
    for (int q = tid; q < KK * KK; q += THREADS) {
        int i = q % KK, j = q / KK;
        if (j > i) {
            float lx = fmaxf(s_bx1[i], s_bx1[j]);
            float ly = fmaxf(s_by1[i], s_by1[j]);
            float rx = fminf(s_bx2[i], s_bx2[j]);
            float ry = fminf(s_by2[i], s_by2[j]);
            float iw = fmaxf(rx - lx, 0.0f), ih = fmaxf(ry - ly, 0.0f);
            float inter = iw * ih;
            float iou = __fdividef(inter, s_ba[i] + s_ba[j] - inter + EPS_);
            if (iou > 0.5f) atomicOr(&s_sup[i][j >> 5], 1u << (j & 31));
        }
    }
    __syncthreads();

    // ---- greedy NMS sweep (exact reference semantics), serial in thread 0 ----
    if (tid == 0) {
        const uint4* supv = (const uint4*)s_sup;
        unsigned kw0 = s_kw[0], kw1 = s_kw[1], kw2 = s_kw[2], kw3 = s_kw[3];
        #pragma unroll 4
        for (int i = 0; i < KK; i++) {
            uint4 r = supv[i];
            unsigned wv = (i < 32) ? kw0 : (i < 64) ? kw1 : (i < 96) ? kw2 : kw3;
            if ((wv >> (i & 31)) & 1u) {
                kw0 &= ~r.x; kw1 &= ~r.y; kw2 &= ~r.z; kw3 &= ~r.w;
            }
        }
        s_kw[0] = kw0; s_kw[1] = kw1; s_kw[2] = kw2; s_kw[3] = kw3;
    }
    __syncthreads();

    // ---- per-target max-IoU argmax over all pairs ----
    // t = q % KK (lane-varying -> conflict-free atomicMax), p = q / KK
    // key = (iou_bits << 32) | ~p -> max iou; ties -> smallest p
    {
        unsigned kw[4] = { s_kw[0], s_kw[1], s_kw[2], s_kw[3] };
        for (int q = tid; q < KK * KK; q += THREADS) {
            int t = q % KK, p = q / KK;
            float kf = ((kw[p >> 5] >> (p & 31)) & 1u) ? 1.0f : 0.0f;
            float lx = fmaxf(s_bx1[p], s_tx1[t]);
            float ly = fmaxf(s_by1[p], s_ty1[t]);
            float rx = fminf(s_bx2[p], s_tx2[t]);
            float ry = fminf(s_by2[p], s_ty2[t]);
            float iw = fmaxf(rx - lx, 0.0f), ih = fmaxf(ry - ly, 0.0f);
            float inter = iw * ih;
            float ta = (s_tx2[t] - s_tx1[t]) * (s_ty2[t] - s_ty1[t]);
            float iou = __fdividef(inter, s_ba[p] + ta - inter + EPS_);
            float v = iou * kf;                  // v >= 0 -> bits monotonic
            unsigned long long key = ((unsigned long long)__float_as_uint(v) << 32)
                                   | (unsigned)(0xFFFFFFFFu - (unsigned)p);
            atomicMax(&s_best[t], key);
        }
    }
    __syncthreads();

    // ---- per-target DIoU + penalty terms ----
    float diou = 0.0f, lowv = 0.0f, highv = 0.0f;
    if (tid < KK) {
        unsigned long long key = s_best[tid];
        float max_iou = fmaxf(__uint_as_float((unsigned)(key >> 32)), 0.0f);
        int best = (int)(0xFFFFFFFFu - (unsigned)(key & 0xFFFFFFFFull));
        float tx1 = s_tx1[tid], ty1 = s_ty1[tid], tx2 = s_tx2[tid], ty2 = s_ty2[tid];
        float pbx1 = s_bx1[best], pby1 = s_by1[best];
        float pbx2 = s_bx2[best], pby2 = s_by2[best];
        float pcx = (pbx1 + pbx2) * 0.5f, pcy = (pby1 + pby2) * 0.5f;
        float tcx = (tx1 + tx2) * 0.5f,  tcy = (ty1 + ty2) * 0.5f;
        float cd = (pcx - tcx) * (pcx - tcx) + (pcy - tcy) * (pcy - tcy);
        float ex1 = fminf(pbx1, tx1), ey1 = fminf(pby1, ty1);
        float ex2 = fmaxf(pbx2, tx2), ey2 = fmaxf(pby2, ty2);
        float dg = (ex2 - ex1) * (ex2 - ex1) + (ey2 - ey1) * (ey2 - ey1);
        diou = 1.0f - (max_iou - __fdividef(cd, dg + EPS_));

        float kfr = ((s_kw[tid >> 5] >> (tid & 31)) & 1u) ? 1.0f : 0.0f;
        float val = s_val[tid];
        lowv  = fmaxf(-val, 0.0f) * kfr;
        highv = fmaxf(val - 1.0f, 0.0f) * kfr;
    }

    // deterministic reduction: warp shuffles + fixed-order smem combine
    #pragma unroll
    for (int off = 16; off; off >>= 1) {
        diou  += __shfl_down_sync(0xFFFFFFFFu, diou,  off);
        lowv  += __shfl_down_sync(0xFFFFFFFFu, lowv,  off);
        highv += __shfl_down_sync(0xFFFFFFFFu, highv, off);
    }
    if ((tid & 31) == 0) {
        s_red[0][tid >> 5] = diou;
        s_red[1][tid >> 5] = lowv;
        s_red[2][tid >> 5] = highv;
    }
    __syncthreads();
    if (tid == 0) {
        float d = 0.0f, l = 0.0f, h = 0.0f;
        #pragma unroll
        for (int w = 0; w < THREADS / 32; w++) {
            d += s_red[0][w]; l += s_red[1][w]; h += s_red[2][w];
        }
        float cnt = (float)(__popc(s_kw[0]) + __popc(s_kw[1]) +
                            __popc(s_kw[2]) + __popc(s_kw[3]));
        g_scratch[img * 4 + 0] = d;
        g_scratch[img * 4 + 1] = l;
        g_scratch[img * 4 + 2] = h;
        g_scratch[img * 4 + 3] = cnt;
        g_cnt[img] = 0;                 // reset for next graph replay
        __threadfence();
        unsigned t = atomicAdd(&g_done, 1u);
        s_last = (t == BB - 1) ? 1 : 0;
    }
    __syncthreads();

    // ---- last image's tail CTA performs the global finalize ----
    if (s_last) {
        __threadfence();
        float d = 0.0f, l = 0.0f, h = 0.0f, c = 0.0f;
        if (tid < BB) {
            d = g_scratch[tid * 4 + 0];
            l = g_scratch[tid * 4 + 1];
            h = g_scratch[tid * 4 + 2];
            c = g_scratch[tid * 4 + 3];
        }
        #pragma unroll
        for (int off = 16; off; off >>= 1) {
            d += __shfl_down_sync(0xFFFFFFFFu, d, off);
            l += __shfl_down_sync(0xFFFFFFFFu, l, off);
            h += __shfl_down_sync(0xFFFFFFFFu, h, off);
            c += __shfl_down_sync(0xFFFFFFFFu, c, off);
        }
        if ((tid & 31) == 0) {
            s_red[0][tid >> 5] = d;
            s_red[1][tid >> 5] = l;
            s_red[2][tid >> 5] = h;
            s_part[tid >> 5]   = __float_as_uint(c);
        }
        __syncthreads();
        if (tid == 0) {
            float D = 0.0f, L = 0.0f, H = 0.0f, Cn = 0.0f;
            #pragma unroll
            for (int w = 0; w < THREADS / 32; w++) {
                D += s_red[0][w]; L += s_red[1][w]; H += s_red[2][w];
                Cn += __uint_as_float(s_part[w]);
            }
            float n = fmaxf(Cn, 1.0f);
            out[0] = D / (float)(BB * KK) + L / n + 0.5f * (H / n);
            g_done = 0;                 // reset for next graph replay
        }
    }
}

extern "C" void kernel_launch(void* const* d_in, const int* in_sizes, int n_in,
                              void* d_out, int out_size)
{
    const float* output  = (const float*)d_in[0];   // (128,64,64,9,5) fp32
    const float* tboxes  = (const float*)d_in[1];   // (128,100,4) fp32
    const float* anchors = (const float*)d_in[2];   // (9,2) fp32
    float* out = (float*)d_out;

    fused_kernel<<<BB * SPLIT, THREADS>>>(output, tboxes, anchors, out);
}

// round 10
// speedup vs baseline: 1.7986x; 1.4645x over previous
#include <cuda_runtime.h>
#include <math.h>

#define BB 128
#define HH 64
#define WW 64
#define AA 9
#define NN (HH*WW*AA)           // 36864 predictions per image
#define KK 100
#define NBUCK 2048
#define CAP 1024                // candidate capacity per image
#define SPLIT 8                 // collect CTAs per image
#define NSEG (NN/SPLIT)         // 4608 elements per collect CTA
#define CTHREADS 256
#define TTHREADS 1024
#define DS_ 1024.0f
#define STRIDE_ 64.0f
#define EPS_ 1e-7f
#define T0_ 1.25f               // static logit collect-threshold (fallback-guarded)

// globals (zero-initialized at load; kernels self-reset for graph replay)
__device__ unsigned long long g_cand[BB][CAP];
__device__ int g_cnt[BB];
__device__ float g_scratch[BB * 4];
__device__ unsigned g_done;

__device__ __forceinline__ unsigned fkey(float x) {
    unsigned u = __float_as_uint(x);
    return (u & 0x80000000u) ? ~u : (u | 0x80000000u);
}

__device__ __forceinline__ unsigned long long make_cand(float x, int e) {
    float conf = 1.0f / (1.0f + __expf(-x));           // conf in (0,1)
    unsigned ck = __float_as_uint(conf) ^ 0x80000000u; // order-preserving (conf>0)
    return ((unsigned long long)ck << 32) | (unsigned)(0xFFFFFFFFu - (unsigned)e);
}

// ---- kernel A: candidate collection (R5-proven, ~17us at 5.5 TB/s eff) ----
__global__ __launch_bounds__(CTHREADS)
void collect_kernel(const float* __restrict__ out5)
{
    const int img = blockIdx.x / SPLIT;
    const int seg = blockIdx.x % SPLIT;
    const float* __restrict__ ip = out5 + (size_t)img * NN * 5;
    const int base = seg * NSEG;

    #pragma unroll 6
    for (int i = threadIdx.x; i < NSEG; i += CTHREADS) {
        int e = base + i;
        float x = __ldg(&ip[(size_t)e * 5 + 4]);
        if (x > T0_) {
            int q = atomicAdd(&g_cnt[img], 1);
            if (q < CAP) g_cand[img][q] = make_cand(x, e);
        }
    }
}

// ---- kernel B: per-image tail at 1024 threads (32 warps for latency hiding) ----
__global__ __launch_bounds__(TTHREADS)
void tail_kernel(const float* __restrict__ out5,
                 const float* __restrict__ tboxes,
                 const float* __restrict__ anchors,
                 float* __restrict__ out)
{
    __shared__ union {
        unsigned hist[NBUCK];                  // fallback only (8KB)
        unsigned long long cand[CAP];          // 8KB
    } u;
    __shared__ unsigned s_part[TTHREADS / 32];
    __shared__ unsigned s_fpart[TTHREADS];     // fallback partial sums
    __shared__ int s_sele[KK];
    __shared__ float s_selc[KK];
    __shared__ float s_bx1[KK], s_by1[KK], s_bx2[KK], s_by2[KK], s_ba[KK], s_val[KK];
    __shared__ float s_tx1[KK], s_ty1[KK], s_tx2[KK], s_ty2[KK];
    __shared__ unsigned long long s_best[KK];
    __shared__ unsigned s_sup[KK][4];
    __shared__ unsigned s_kw[4];
    __shared__ int s_cnt, s_bsel, s_last;
    __shared__ float s_anc[AA * 2];
    __shared__ float s_red[3][TTHREADS / 32];

    const int tid = threadIdx.x;
    const int img = blockIdx.x;
    const float* __restrict__ ip = out5 + (size_t)img * NN * 5;

    if (tid < AA * 2) s_anc[tid] = anchors[tid];
    if (tid == 0) { s_kw[0] = s_kw[1] = s_kw[2] = s_kw[3] = 0; }
    if (tid < KK * 4) ((unsigned*)s_sup)[tid] = 0;

    const int gcnt = g_cnt[img];
    if (tid == 0) s_cnt = gcnt;
    {
        int C0 = min(gcnt, CAP);
        for (int i = tid; i < C0; i += TTHREADS) u.cand[i] = g_cand[img][i];
    }
    __syncthreads();

    // ---- fallback: exact histogram top-K (never taken for typical inputs) ----
    if (gcnt < KK || gcnt > CAP) {
        for (int i = tid; i < NBUCK; i += TTHREADS) u.hist[i] = 0;
        if (tid == 0) s_cnt = 0;
        __syncthreads();
        for (int e = tid; e < NN; e += TTHREADS) {
            float x = ip[(size_t)e * 5 + 4];
            atomicAdd(&u.hist[fkey(x) >> 21], 1u);
        }
        __syncthreads();
        {
            unsigned s = 0;
            int base = tid * (NBUCK / TTHREADS);
            #pragma unroll
            for (int j = 0; j < NBUCK / TTHREADS; j++) s += u.hist[base + j];
            s_fpart[tid] = s;
        }
        __syncthreads();
        if (tid == 0) {
            unsigned cum = 0; int sg = 0;
            for (int t = TTHREADS - 1; t >= 0; t--) {
                if (cum + s_fpart[t] >= KK) { sg = t; break; }
                cum += s_fpart[t];
            }
            int bsel = sg * (NBUCK / TTHREADS);
            for (int b = sg * (NBUCK / TTHREADS) + (NBUCK / TTHREADS) - 1;
                 b >= sg * (NBUCK / TTHREADS); b--) {
                cum += u.hist[b];
                if (cum >= KK) { bsel = b; break; }
            }
            s_bsel = bsel;
        }
        __syncthreads();
        const int bsel = s_bsel;
        for (int e = tid; e < NN; e += TTHREADS) {
            float x = ip[(size_t)e * 5 + 4];
            if ((int)(fkey(x) >> 21) >= bsel) {
                int pos = atomicAdd(&s_cnt, 1);
                if (pos < CAP) u.cand[pos] = make_cand(x, e);
            }
        }
        __syncthreads();
    }

    const int C = min(s_cnt, CAP);

    // ---- rank selection: exact top-K without sort (keys unique) ----
    for (int c = tid; c < C; c += TTHREADS) {
        unsigned long long key = u.cand[c];
        int rank = 0;
        #pragma unroll 4
        for (int j = 0; j < C; j++) rank += (u.cand[j] > key) ? 1 : 0;
        if (rank < KK) {
            s_sele[rank] = (int)(0xFFFFFFFFu - (unsigned)(key & 0xFFFFFFFFull));
            s_selc[rank] = __uint_as_float((unsigned)(key >> 32) ^ 0x80000000u);
        }
    }
    __syncthreads();

    // ---- build top-K boxes (clip + fix), cmask, targets ----
    if (tid < KK) {
        int e = s_sele[tid];
        float conf = s_selc[tid];
        float o0 = ip[(size_t)e * 5 + 0], o1 = ip[(size_t)e * 5 + 1];
        float o2 = ip[(size_t)e * 5 + 2], o3 = ip[(size_t)e * 5 + 3];
        int a = e % AA;
        int w = (e / AA) % WW;
        int h = e / (AA * WW);
        float px = (1.0f / (1.0f + __expf(-o0)) + (float)w) * STRIDE_;
        float py = (1.0f / (1.0f + __expf(-o1)) + (float)h) * STRIDE_;
        float pw = __expf(o2) * s_anc[a * 2 + 0] * DS_;
        float ph = __expf(o3) * s_anc[a * 2 + 1] * DS_;
        float c0 = px - pw * 0.5f, c1 = py - ph * 0.5f;
        float c2 = px + pw * 0.5f, c3 = py + ph * 0.5f;
        c0 = fminf(fmaxf(c0, 0.0f), DS_); c1 = fminf(fmaxf(c1, 0.0f), DS_);
        c2 = fminf(fmaxf(c2, 0.0f), DS_); c3 = fminf(fmaxf(c3, 0.0f), DS_);
        float x1 = fminf(c0, c2), x2 = fmaxf(c0, c2);
        float y1 = fminf(c1, c3), y2 = fmaxf(c1, c3);
        if (x1 == x2) x2 = x1 + 1.0f;
        if (y1 == y2) y2 = y1 + 1.0f;
        s_bx1[tid] = x1; s_by1[tid] = y1; s_bx2[tid] = x2; s_by2[tid] = y2;
        s_ba[tid] = (x2 - x1) * (y2 - y1);
        s_val[tid] = conf;
        if (conf >= 0.5f) atomicOr(&s_kw[tid >> 5], 1u << (tid & 31));

        const float* tp = tboxes + ((size_t)img * KK + tid) * 4;
        float t0 = fminf(fmaxf(tp[0], 0.0f), DS_);
        float t1 = fminf(fmaxf(tp[1], 0.0f), DS_);
        float t2 = fminf(fmaxf(tp[2], 0.0f), DS_);
        float t3 = fminf(fmaxf(tp[3], 0.0f), DS_);
        float tx1 = fminf(t0, t2), tx2 = fmaxf(t0, t2);
        float ty1 = fminf(t1, t3), ty2 = fmaxf(t1, t3);
        if (tx1 == tx2) tx2 = tx1 + 1.0f;
        if (ty1 == ty2) ty2 = ty1 + 1.0f;
        s_tx1[tid] = tx1; s_ty1[tid] = ty1; s_tx2[tid] = tx2; s_ty2[tid] = ty2;
    }
    __syncthreads();

    // ---- pairwise pred-pred suppression bitmask (conditional atomics, rare) ----
    for (int q = tid; q < KK * KK; q += TTHREADS) {
        int i = q % KK, j = q / KK;
        if (j > i) {
            float lx = fmaxf(s_bx1[i], s_bx1[j]);
            float ly = fmaxf(s_by1[i], s_by1[j]);
            float rx = fminf(s_bx2[i], s_bx2[j]);
            float ry = fminf(s_by2[i], s_by2[j]);
            float iw = fmaxf(rx - lx, 0.0f), ih = fmaxf(ry - ly, 0.0f);
            float inter = iw * ih;
            float iou = __fdividef(inter, s_ba[i] + s_ba[j] - inter + EPS_);
            if (iou > 0.5f) atomicOr(&s_sup[i][j >> 5], 1u << (j & 31));
        }
    }
    __syncthreads();

    // ---- greedy NMS sweep (exact reference semantics), serial in thread 0 ----
    if (tid == 0) {
        const uint4* supv = (const uint4*)s_sup;
        unsigned kw0 = s_kw[0], kw1 = s_kw[1], kw2 = s_kw[2], kw3 = s_kw[3];
        #pragma unroll 4
        for (int i = 0; i < KK; i++) {
            uint4 r = supv[i];
            unsigned wv = (i < 32) ? kw0 : (i < 64) ? kw1 : (i < 96) ? kw2 : kw3;
            if ((wv >> (i & 31)) & 1u) {
                kw0 &= ~r.x; kw1 &= ~r.y; kw2 &= ~r.z; kw3 &= ~r.w;
            }
        }
        s_kw[0] = kw0; s_kw[1] = kw1; s_kw[2] = kw2; s_kw[3] = kw3;
    }
    __syncthreads();

    // ---- per-target max-IoU argmax: warp-owned targets, shuffle reduce, no atomics
    // warp w handles t = w, w+32, ...; lane l covers p = l, l+32, l+64, l+96
    // key = (iou_bits << 32) | ~p -> max iou; ties -> smallest p
    {
        const int w = tid >> 5, l = tid & 31;
        unsigned kw[4] = { s_kw[0], s_kw[1], s_kw[2], s_kw[3] };
        for (int t = w; t < KK; t += TTHREADS / 32) {
            float tx1 = s_tx1[t], ty1 = s_ty1[t], tx2 = s_tx2[t], ty2 = s_ty2[t];
            float ta = (tx2 - tx1) * (ty2 - ty1);
            unsigned long long best = 0ull;
            #pragma unroll
            for (int p = l; p < KK + 28; p += 32) {
                if (p < KK) {
                    float kf = ((kw[p >> 5] >> (p & 31)) & 1u) ? 1.0f : 0.0f;
                    float lx = fmaxf(s_bx1[p], tx1);
                    float ly = fmaxf(s_by1[p], ty1);
                    float rx = fminf(s_bx2[p], tx2);
                    float ry = fminf(s_by2[p], ty2);
                    float iw = fmaxf(rx - lx, 0.0f), ih = fmaxf(ry - ly, 0.0f);
                    float inter = iw * ih;
                    float iou = __fdividef(inter, s_ba[p] + ta - inter + EPS_);
                    float v = iou * kf;
                    unsigned long long key =
                        ((unsigned long long)__float_as_uint(v) << 32)
                        | (unsigned)(0xFFFFFFFFu - (unsigned)p);
                    best = (key > best) ? key : best;
                }
            }
            #pragma unroll
            for (int off = 16; off; off >>= 1) {
                unsigned long long o = __shfl_down_sync(0xFFFFFFFFu, best, off);
                best = (o > best) ? o : best;
            }
            if (l == 0) s_best[t] = best;
        }
    }
    __syncthreads();

    // ---- per-target DIoU + penalty terms ----
    float diou = 0.0f, lowv = 0.0f, highv = 0.0f;
    if (tid < KK) {
        unsigned long long key = s_best[tid];
        float max_iou = fmaxf(__uint_as_float((unsigned)(key >> 32)), 0.0f);
        int best = (int)(0xFFFFFFFFu - (unsigned)(key & 0xFFFFFFFFull));
        float tx1 = s_tx1[tid], ty1 = s_ty1[tid], tx2 = s_tx2[tid], ty2 = s_ty2[tid];
        float pbx1 = s_bx1[best], pby1 = s_by1[best];
        float pbx2 = s_bx2[best], pby2 = s_by2[best];
        float pcx = (pbx1 + pbx2) * 0.5f, pcy = (pby1 + pby2) * 0.5f;
        float tcx = (tx1 + tx2) * 0.5f,  tcy = (ty1 + ty2) * 0.5f;
        float cd = (pcx - tcx) * (pcx - tcx) + (pcy - tcy) * (pcy - tcy);
        float ex1 = fminf(pbx1, tx1), ey1 = fminf(pby1, ty1);
        float ex2 = fmaxf(pbx2, tx2), ey2 = fmaxf(pby2, ty2);
        float dg = (ex2 - ex1) * (ex2 - ex1) + (ey2 - ey1) * (ey2 - ey1);
        diou = 1.0f - (max_iou - __fdividef(cd, dg + EPS_));

        float kfr = ((s_kw[tid >> 5] >> (tid & 31)) & 1u) ? 1.0f : 0.0f;
        float val = s_val[tid];
        lowv  = fmaxf(-val, 0.0f) * kfr;
        highv = fmaxf(val - 1.0f, 0.0f) * kfr;
    }

    // deterministic reduction
    #pragma unroll
    for (int off = 16; off; off >>= 1) {
        diou  += __shfl_down_sync(0xFFFFFFFFu, diou,  off);
        lowv  += __shfl_down_sync(0xFFFFFFFFu, lowv,  off);
        highv += __shfl_down_sync(0xFFFFFFFFu, highv, off);
    }
    if ((tid & 31) == 0) {
        s_red[0][tid >> 5] = diou;
        s_red[1][tid >> 5] = lowv;
        s_red[2][tid >> 5] = highv;
    }
    __syncthreads();
    if (tid == 0) {
        float d = 0.0f, l = 0.0f, h = 0.0f;
        #pragma unroll
        for (int w = 0; w < 4; w++) {           // only warps 0-3 hold tid<KK data
            d += s_red[0][w]; l += s_red[1][w]; h += s_red[2][w];
        }
        float cnt = (float)(__popc(s_kw[0]) + __popc(s_kw[1]) +
                            __popc(s_kw[2]) + __popc(s_kw[3]));
        g_scratch[img * 4 + 0] = d;
        g_scratch[img * 4 + 1] = l;
        g_scratch[img * 4 + 2] = h;
        g_scratch[img * 4 + 3] = cnt;
        g_cnt[img] = 0;                 // reset for next graph replay
        __threadfence();
        unsigned t = atomicAdd(&g_done, 1u);
        s_last = (t == BB - 1) ? 1 : 0;
    }
    __syncthreads();

    // ---- last CTA performs the global finalize ----
    if (s_last) {
        __threadfence();
        float d = 0.0f, l = 0.0f, h = 0.0f, c = 0.0f;
        if (tid < BB) {
            d = g_scratch[tid * 4 + 0];
            l = g_scratch[tid * 4 + 1];
            h = g_scratch[tid * 4 + 2];
            c = g_scratch[tid * 4 + 3];
        }
        #pragma unroll
        for (int off = 16; off; off >>= 1) {
            d += __shfl_down_sync(0xFFFFFFFFu, d, off);
            l += __shfl_down_sync(0xFFFFFFFFu, l, off);
            h += __shfl_down_sync(0xFFFFFFFFu, h, off);
            c += __shfl_down_sync(0xFFFFFFFFu, c, off);
        }
        if ((tid & 31) == 0) {
            s_red[0][tid >> 5] = d;
            s_red[1][tid >> 5] = l;
            s_red[2][tid >> 5] = h;
            s_part[tid >> 5]   = __float_as_uint(c);
        }
        __syncthreads();
        if (tid == 0) {
            float D = 0.0f, L = 0.0f, H = 0.0f, Cn = 0.0f;
            #pragma unroll
            for (int w = 0; w < 4; w++) {       // only warps 0-3 hold tid<BB data
                D += s_red[0][w]; L += s_red[1][w]; H += s_red[2][w];
                Cn += __uint_as_float(s_part[w]);
            }
            float n = fmaxf(Cn, 1.0f);
            out[0] = D / (float)(BB * KK) + L / n + 0.5f * (H / n);
            g_done = 0;                 // reset for next graph replay
        }
    }
}

extern "C" void kernel_launch(void* const* d_in, const int* in_sizes, int n_in,
                              void* d_out, int out_size)
{
    const float* output  = (const float*)d_in[0];   // (128,64,64,9,5) fp32
    const float* tboxes  = (const float*)d_in[1];   // (128,100,4) fp32
    const float* anchors = (const float*)d_in[2];   // (9,2) fp32
    float* out = (float*)d_out;

    collect_kernel<<<BB * SPLIT, CTHREADS>>>(output);
    tail_kernel<<<BB, TTHREADS>>>(output, tboxes, anchors, out);
}

// round 11
// speedup vs baseline: 1.8932x; 1.0526x over previous
#include <cuda_runtime.h>
#include <math.h>

#define BB 128
#define HH 64
#define WW 64
#define AA 9
#define NN (HH*WW*AA)           // 36864 predictions per image
#define KK 100
#define NBUCK 2048
#define CAP 1024                // candidate capacity per image
#define SPLIT 8                 // collect CTAs per image
#define NSEG (NN/SPLIT)         // 4608 elements per collect CTA
#define CTHREADS 256
#define TTHREADS 1024
#define DS_ 1024.0f
#define STRIDE_ 64.0f
#define EPS_ 1e-7f
#define T0_ 1.25f               // static logit collect-threshold (fallback-guarded)

// globals (zero-initialized at load; kernels self-reset for graph replay)
__device__ unsigned long long g_key[BB][CAP];
__device__ float4 g_box[BB][CAP];
__device__ int g_cnt[BB];
__device__ float g_scratch[BB * 4];
__device__ unsigned g_done;

__device__ __forceinline__ unsigned fkey(float x) {
    unsigned u = __float_as_uint(x);
    return (u & 0x80000000u) ? ~u : (u | 0x80000000u);
}

__device__ __forceinline__ unsigned long long make_cand(float x, int e) {
    float conf = 1.0f / (1.0f + __expf(-x));           // conf in (0,1)
    unsigned ck = __float_as_uint(conf) ^ 0x80000000u; // order-preserving (conf>0)
    return ((unsigned long long)ck << 32) | (unsigned)(0xFFFFFFFFu - (unsigned)e);
}

// build clipped+fixed box corners for record e of image slice ip
__device__ __forceinline__ float4 build_box(const float* __restrict__ ip,
                                            const float* __restrict__ anc, int e) {
    const float* rec = ip + (size_t)e * 5;
    float o0 = __ldg(rec + 0), o1 = __ldg(rec + 1);
    float o2 = __ldg(rec + 2), o3 = __ldg(rec + 3);
    int a = e % AA;
    int w = (e / AA) % WW;
    int h = e / (AA * WW);
    float px = (1.0f / (1.0f + __expf(-o0)) + (float)w) * STRIDE_;
    float py = (1.0f / (1.0f + __expf(-o1)) + (float)h) * STRIDE_;
    float pw = __expf(o2) * __ldg(anc + 2 * a + 0) * DS_;
    float ph = __expf(o3) * __ldg(anc + 2 * a + 1) * DS_;
    float c0 = px - pw * 0.5f, c1 = py - ph * 0.5f;
    float c2 = px + pw * 0.5f, c3 = py + ph * 0.5f;
    c0 = fminf(fmaxf(c0, 0.0f), DS_); c1 = fminf(fmaxf(c1, 0.0f), DS_);
    c2 = fminf(fmaxf(c2, 0.0f), DS_); c3 = fminf(fmaxf(c3, 0.0f), DS_);
    float x1 = fminf(c0, c2), x2 = fmaxf(c0, c2);
    float y1 = fminf(c1, c3), y2 = fmaxf(c1, c3);
    if (x1 == x2) x2 = x1 + 1.0f;
    if (y1 == y2) y2 = y1 + 1.0f;
    return make_float4(x1, y1, x2, y2);
}

// ---- kernel A: candidate collection + box construction (BW-bound stream) ----
__global__ __launch_bounds__(CTHREADS)
void collect_kernel(const float* __restrict__ out5,
                    const float* __restrict__ anchors)
{
    const int img = blockIdx.x / SPLIT;
    const int seg = blockIdx.x % SPLIT;
    const float* __restrict__ ip = out5 + (size_t)img * NN * 5;
    const int base = seg * NSEG;

    #pragma unroll 6
    for (int i = threadIdx.x; i < NSEG; i += CTHREADS) {
        int e = base + i;
        float x = __ldg(&ip[(size_t)e * 5 + 4]);
        if (x > T0_) {
            int q = atomicAdd(&g_cnt[img], 1);
            if (q < CAP) {
                g_key[img][q] = make_cand(x, e);
                g_box[img][q] = build_box(ip, anchors, e);
            }
        }
    }
}

// ---- kernel B: per-image tail at 1024 threads ----
__global__ __launch_bounds__(TTHREADS)
void tail_kernel(const float* __restrict__ out5,
                 const float* __restrict__ tboxes,
                 const float* __restrict__ anchors,
                 float* __restrict__ out)
{
    __shared__ union {
        unsigned hist[NBUCK];                  // fallback only (8KB)
        unsigned long long cand[CAP];          // 8KB
    } u;
    __shared__ unsigned s_part[TTHREADS / 32];
    __shared__ unsigned s_fpart[TTHREADS];     // fallback partial sums
    __shared__ int s_sele[KK];
    __shared__ float s_selc[KK];
    __shared__ float s_bx1[KK], s_by1[KK], s_bx2[KK], s_by2[KK], s_ba[KK];
    __shared__ float s_tx1[KK], s_ty1[KK], s_tx2[KK], s_ty2[KK];
    __shared__ unsigned long long s_best[KK];
    __shared__ unsigned s_sup[KK][4];
    __shared__ unsigned s_kw[4];
    __shared__ int s_cnt, s_bsel, s_last;
    __shared__ float s_red[3][TTHREADS / 32];

    const int tid = threadIdx.x;
    const int img = blockIdx.x;
    const float* __restrict__ ip = out5 + (size_t)img * NN * 5;

    if (tid == 0) { s_kw[0] = s_kw[1] = s_kw[2] = s_kw[3] = 0; }
    if (tid < KK * 4) ((unsigned*)s_sup)[tid] = 0;

    // targets first: DRAM latency overlaps key fetch + rank selection
    if (tid < KK) {
        const float* tp = tboxes + ((size_t)img * KK + tid) * 4;
        float t0 = fminf(fmaxf(__ldg(tp + 0), 0.0f), DS_);
        float t1 = fminf(fmaxf(__ldg(tp + 1), 0.0f), DS_);
        float t2 = fminf(fmaxf(__ldg(tp + 2), 0.0f), DS_);
        float t3 = fminf(fmaxf(__ldg(tp + 3), 0.0f), DS_);
        float tx1 = fminf(t0, t2), tx2 = fmaxf(t0, t2);
        float ty1 = fminf(t1, t3), ty2 = fmaxf(t1, t3);
        if (tx1 == tx2) tx2 = tx1 + 1.0f;
        if (ty1 == ty2) ty2 = ty1 + 1.0f;
        s_tx1[tid] = tx1; s_ty1[tid] = ty1; s_tx2[tid] = tx2; s_ty2[tid] = ty2;
    }

    const int gcnt = g_cnt[img];
    if (tid == 0) s_cnt = gcnt;
    {
        int C0 = min(gcnt, CAP);
        for (int i = tid; i < C0; i += TTHREADS) u.cand[i] = g_key[img][i];
    }
    __syncthreads();

    const bool fb = (gcnt < KK || gcnt > CAP);

    // ---- fallback: exact histogram top-K (never taken for typical inputs) ----
    if (fb) {
        for (int i = tid; i < NBUCK; i += TTHREADS) u.hist[i] = 0;
        if (tid == 0) s_cnt = 0;
        __syncthreads();
        for (int e = tid; e < NN; e += TTHREADS) {
            float x = ip[(size_t)e * 5 + 4];
            atomicAdd(&u.hist[fkey(x) >> 21], 1u);
        }
        __syncthreads();
        {
            unsigned s = 0;
            int base = tid * (NBUCK / TTHREADS);
            #pragma unroll
            for (int j = 0; j < NBUCK / TTHREADS; j++) s += u.hist[base + j];
            s_fpart[tid] = s;
        }
        __syncthreads();
        if (tid == 0) {
            unsigned cum = 0; int sg = 0;
            for (int t = TTHREADS - 1; t >= 0; t--) {
                if (cum + s_fpart[t] >= KK) { sg = t; break; }
                cum += s_fpart[t];
            }
            int bsel = sg * (NBUCK / TTHREADS);
            for (int b = sg * (NBUCK / TTHREADS) + (NBUCK / TTHREADS) - 1;
                 b >= sg * (NBUCK / TTHREADS); b--) {
                cum += u.hist[b];
                if (cum >= KK) { bsel = b; break; }
            }
            s_bsel = bsel;
        }
        __syncthreads();
        const int bsel = s_bsel;
        for (int e = tid; e < NN; e += TTHREADS) {
            float x = ip[(size_t)e * 5 + 4];
            if ((int)(fkey(x) >> 21) >= bsel) {
                int pos = atomicAdd(&s_cnt, 1);
                if (pos < CAP) u.cand[pos] = make_cand(x, e);
            }
        }
        __syncthreads();
    }

    const int C = min(s_cnt, CAP);

    // ---- rank selection (keys unique); main path gathers prebuilt boxes ----
    for (int c = tid; c < C; c += TTHREADS) {
        unsigned long long key = u.cand[c];
        int rank = 0;
        #pragma unroll 4
        for (int j = 0; j < C; j++) rank += (u.cand[j] > key) ? 1 : 0;
        if (rank < KK) {
            s_sele[rank] = (int)(0xFFFFFFFFu - (unsigned)(key & 0xFFFFFFFFull));
            s_selc[rank] = __uint_as_float((unsigned)(key >> 32) ^ 0x80000000u);
            if (!fb) {
                float4 b = g_box[img][c];          // L2-resident
                s_bx1[rank] = b.x; s_by1[rank] = b.y;
                s_bx2[rank] = b.z; s_by2[rank] = b.w;
            }
        }
    }
    __syncthreads();

    // fallback path must build boxes from raw records
    if (fb && tid < KK) {
        float4 b = build_box(ip, anchors, s_sele[tid]);
        s_bx1[tid] = b.x; s_by1[tid] = b.y; s_bx2[tid] = b.z; s_by2[tid] = b.w;
    }
    if (fb) __syncthreads();

    if (tid < KK) {
        s_ba[tid] = (s_bx2[tid] - s_bx1[tid]) * (s_by2[tid] - s_by1[tid]);
        if (s_selc[tid] >= 0.5f) atomicOr(&s_kw[tid >> 5], 1u << (tid & 31));
    }
    __syncthreads();

    // ---- pairwise pred-pred suppression bitmask (conditional atomics, rare) ----
    for (int q = tid; q < KK * KK; q += TTHREADS) {
        int i = q % KK, j = q / KK;
        if (j > i) {
            float lx = fmaxf(s_bx1[i], s_bx1[j]);
            float ly = fmaxf(s_by1[i], s_by1[j]);
            float rx = fminf(s_bx2[i], s_bx2[j]);
            float ry = fminf(s_by2[i], s_by2[j]);
            float iw = fmaxf(rx - lx, 0.0f), ih = fmaxf(ry - ly, 0.0f);
            float inter = iw * ih;
            float iou = __fdividef(inter, s_ba[i] + s_ba[j] - inter + EPS_);
            if (iou > 0.5f) atomicOr(&s_sup[i][j >> 5], 1u << (j & 31));
        }
    }
    __syncthreads();

    // ---- greedy NMS sweep (exact reference semantics), serial in thread 0 ----
    if (tid == 0) {
        const uint4* supv = (const uint4*)s_sup;
        unsigned kw0 = s_kw[0], kw1 = s_kw[1], kw2 = s_kw[2], kw3 = s_kw[3];
        #pragma unroll 4
        for (int i = 0; i < KK; i++) {
            uint4 r = supv[i];
            unsigned wv = (i < 32) ? kw0 : (i < 64) ? kw1 : (i < 96) ? kw2 : kw3;
            if ((wv >> (i & 31)) & 1u) {
                kw0 &= ~r.x; kw1 &= ~r.y; kw2 &= ~r.z; kw3 &= ~r.w;
            }
        }
        s_kw[0] = kw0; s_kw[1] = kw1; s_kw[2] = kw2; s_kw[3] = kw3;
    }
    __syncthreads();

    // ---- per-target max-IoU argmax: warp-owned targets, shuffle reduce ----
    {
        const int w = tid >> 5, l = tid & 31;
        unsigned kw[4] = { s_kw[0], s_kw[1], s_kw[2], s_kw[3] };
        for (int t = w; t < KK; t += TTHREADS / 32) {
            float tx1 = s_tx1[t], ty1 = s_ty1[t], tx2 = s_tx2[t], ty2 = s_ty2[t];
            float ta = (tx2 - tx1) * (ty2 - ty1);
            unsigned long long best = 0ull;
            #pragma unroll
            for (int p = l; p < KK + 28; p += 32) {
                if (p < KK) {
                    float kf = ((kw[p >> 5] >> (p & 31)) & 1u) ? 1.0f : 0.0f;
                    float lx = fmaxf(s_bx1[p], tx1);
                    float ly = fmaxf(s_by1[p], ty1);
                    float rx = fminf(s_bx2[p], tx2);
                    float ry = fminf(s_by2[p], ty2);
                    float iw = fmaxf(rx - lx, 0.0f), ih = fmaxf(ry - ly, 0.0f);
                    float inter = iw * ih;
                    float iou = __fdividef(inter, s_ba[p] + ta - inter + EPS_);
                    float v = iou * kf;
                    unsigned long long key =
                        ((unsigned long long)__float_as_uint(v) << 32)
                        | (unsigned)(0xFFFFFFFFu - (unsigned)p);
                    best = (key > best) ? key : best;
                }
            }
            #pragma unroll
            for (int off = 16; off; off >>= 1) {
                unsigned long long o = __shfl_down_sync(0xFFFFFFFFu, best, off);
                best = (o > best) ? o : best;
            }
            if (l == 0) s_best[t] = best;
        }
    }
    __syncthreads();

    // ---- per-target DIoU + penalty terms ----
    float diou = 0.0f, lowv = 0.0f, highv = 0.0f;
    if (tid < KK) {
        unsigned long long key = s_best[tid];
        float max_iou = fmaxf(__uint_as_float((unsigned)(key >> 32)), 0.0f);
        int best = (int)(0xFFFFFFFFu - (unsigned)(key & 0xFFFFFFFFull));
        float tx1 = s_tx1[tid], ty1 = s_ty1[tid], tx2 = s_tx2[tid], ty2 = s_ty2[tid];
        float pbx1 = s_bx1[best], pby1 = s_by1[best];
        float pbx2 = s_bx2[best], pby2 = s_by2[best];
        float pcx = (pbx1 + pbx2) * 0.5f, pcy = (pby1 + pby2) * 0.5f;
        float tcx = (tx1 + tx2) * 0.5f,  tcy = (ty1 + ty2) * 0.5f;
        float cd = (pcx - tcx) * (pcx - tcx) + (pcy - tcy) * (pcy - tcy);
        float ex1 = fminf(pbx1, tx1), ey1 = fminf(pby1, ty1);
        float ex2 = fmaxf(pbx2, tx2), ey2 = fmaxf(pby2, ty2);
        float dg = (ex2 - ex1) * (ex2 - ex1) + (ey2 - ey1) * (ey2 - ey1);
        diou = 1.0f - (max_iou - __fdividef(cd, dg + EPS_));

        float kfr = ((s_kw[tid >> 5] >> (tid & 31)) & 1u) ? 1.0f : 0.0f;
        float val = s_selc[tid];
        lowv  = fmaxf(-val, 0.0f) * kfr;
        highv = fmaxf(val - 1.0f, 0.0f) * kfr;
    }

    // deterministic reduction
    #pragma unroll
    for (int off = 16; off; off >>= 1) {
        diou  += __shfl_down_sync(0xFFFFFFFFu, diou,  off);
        lowv  += __shfl_down_sync(0xFFFFFFFFu, lowv,  off);
        highv += __shfl_down_sync(0xFFFFFFFFu, highv, off);
    }
    if ((tid & 31) == 0) {
        s_red[0][tid >> 5] = diou;
        s_red[1][tid >> 5] = lowv;
        s_red[2][tid >> 5] = highv;
    }
    __syncthreads();
    if (tid == 0) {
        float d = 0.0f, l = 0.0f, h = 0.0f;
        #pragma unroll
        for (int w = 0; w < 4; w++) {           // only warps 0-3 hold tid<KK data
            d += s_red[0][w]; l += s_red[1][w]; h += s_red[2][w];
        }
        float cnt = (float)(__popc(s_kw[0]) + __popc(s_kw[1]) +
                            __popc(s_kw[2]) + __popc(s_kw[3]));
        g_scratch[img * 4 + 0] = d;
        g_scratch[img * 4 + 1] = l;
        g_scratch[img * 4 + 2] = h;
        g_scratch[img * 4 + 3] = cnt;
        g_cnt[img] = 0;                 // reset for next graph replay
        __threadfence();
        unsigned t = atomicAdd(&g_done, 1u);
        s_last = (t == BB - 1) ? 1 : 0;
    }
    __syncthreads();

    // ---- last CTA performs the global finalize ----
    if (s_last) {
        __threadfence();
        float d = 0.0f, l = 0.0f, h = 0.0f, c = 0.0f;
        if (tid < BB) {
            d = g_scratch[tid * 4 + 0];
            l = g_scratch[tid * 4 + 1];
            h = g_scratch[tid * 4 + 2];
            c = g_scratch[tid * 4 + 3];
        }
        #pragma unroll
        for (int off = 16; off; off >>= 1) {
            d += __shfl_down_sync(0xFFFFFFFFu, d, off);
            l += __shfl_down_sync(0xFFFFFFFFu, l, off);
            h += __shfl_down_sync(0xFFFFFFFFu, h, off);
            c += __shfl_down_sync(0xFFFFFFFFu, c, off);
        }
        if ((tid & 31) == 0) {
            s_red[0][tid >> 5] = d;
            s_red[1][tid >> 5] = l;
            s_red[2][tid >> 5] = h;
            s_part[tid >> 5]   = __float_as_uint(c);
        }
        __syncthreads();
        if (tid == 0) {
            float D = 0.0f, L = 0.0f, H = 0.0f, Cn = 0.0f;
            #pragma unroll
            for (int w = 0; w < 4; w++) {       // only warps 0-3 hold tid<BB data
                D += s_red[0][w]; L += s_red[1][w]; H += s_red[2][w];
                Cn += __uint_as_float(s_part[w]);
            }
            float n = fmaxf(Cn, 1.0f);
            out[0] = D / (float)(BB * KK) + L / n + 0.5f * (H / n);
            g_done = 0;                 // reset for next graph replay
        }
    }
}

extern "C" void kernel_launch(void* const* d_in, const int* in_sizes, int n_in,
                              void* d_out, int out_size)
{
    const float* output  = (const float*)d_in[0];   // (128,64,64,9,5) fp32
    const float* tboxes  = (const float*)d_in[1];   // (128,100,4) fp32
    const float* anchors = (const float*)d_in[2];   // (9,2) fp32
    float* out = (float*)d_out;

    collect_kernel<<<BB * SPLIT, CTHREADS>>>(output, anchors);
    tail_kernel<<<BB, TTHREADS>>>(output, tboxes, anchors, out);
}

// round 12
// speedup vs baseline: 2.1413x; 1.1310x over previous
#include <cuda_runtime.h>
#include <math.h>

#define BB 128
#define HH 64
#define WW 64
#define AA 9
#define NN (HH*WW*AA)           // 36864 predictions per image
#define KK 100
#define NBUCK 2048
#define CAP 1024                // candidate capacity per image
#define THREADS 1024
#define DS_ 1024.0f
#define STRIDE_ 64.0f
#define EPS_ 1e-7f
#define T0_ 1.25f               // static logit collect-threshold (fallback-guarded)

// globals (zero-initialized at load; kernel self-resets for graph replay)
__device__ float g_scratch[BB * 4];
__device__ unsigned g_done;

__device__ __forceinline__ unsigned fkey(float x) {
    unsigned u = __float_as_uint(x);
    return (u & 0x80000000u) ? ~u : (u | 0x80000000u);
}

__device__ __forceinline__ unsigned long long make_cand(float x, int e) {
    float conf = 1.0f / (1.0f + __expf(-x));           // conf in (0,1)
    unsigned ck = __float_as_uint(conf) ^ 0x80000000u; // order-preserving (conf>0)
    return ((unsigned long long)ck << 32) | (unsigned)(0xFFFFFFFFu - (unsigned)e);
}

// build clipped+fixed box corners for record e of image slice ip
__device__ __forceinline__ float4 build_box(const float* __restrict__ ip,
                                            const float* __restrict__ anc, int e) {
    const float* rec = ip + (size_t)e * 5;
    float o0 = __ldg(rec + 0), o1 = __ldg(rec + 1);
    float o2 = __ldg(rec + 2), o3 = __ldg(rec + 3);
    int a = e % AA;
    int w = (e / AA) % WW;
    int h = e / (AA * WW);
    float px = (1.0f / (1.0f + __expf(-o0)) + (float)w) * STRIDE_;
    float py = (1.0f / (1.0f + __expf(-o1)) + (float)h) * STRIDE_;
    float pw = __expf(o2) * __ldg(anc + 2 * a + 0) * DS_;
    float ph = __expf(o3) * __ldg(anc + 2 * a + 1) * DS_;
    float c0 = px - pw * 0.5f, c1 = py - ph * 0.5f;
    float c2 = px + pw * 0.5f, c3 = py + ph * 0.5f;
    c0 = fminf(fmaxf(c0, 0.0f), DS_); c1 = fminf(fmaxf(c1, 0.0f), DS_);
    c2 = fminf(fmaxf(c2, 0.0f), DS_); c3 = fminf(fmaxf(c3, 0.0f), DS_);
    float x1 = fminf(c0, c2), x2 = fmaxf(c0, c2);
    float y1 = fminf(c1, c3), y2 = fmaxf(c1, c3);
    if (x1 == x2) x2 = x1 + 1.0f;
    if (y1 == y2) y2 = y1 + 1.0f;
    return make_float4(x1, y1, x2, y2);
}

__global__ __launch_bounds__(THREADS)
void fused_kernel(const float* __restrict__ out5,
                  const float* __restrict__ tboxes,
                  const float* __restrict__ anchors,
                  float* __restrict__ out)
{
    __shared__ unsigned long long s_key[CAP];          // 8KB
    __shared__ float4 s_box[CAP];                      // 16KB
    __shared__ unsigned s_hist[NBUCK];                 // 8KB (fallback only)
    __shared__ unsigned s_fpart[THREADS / 32];
    __shared__ int s_sele[KK];
    __shared__ float s_selc[KK];
    __shared__ float s_bx1[KK], s_by1[KK], s_bx2[KK], s_by2[KK], s_ba[KK];
    __shared__ float s_tx1[KK], s_ty1[KK], s_tx2[KK], s_ty2[KK];
    __shared__ unsigned long long s_best[KK];
    __shared__ unsigned s_sup[KK][4];
    __shared__ unsigned s_kw[4];
    __shared__ int s_cnt, s_bsel, s_last;
    __shared__ float s_red[3][THREADS / 32];
    __shared__ unsigned s_cpart[THREADS / 32];

    const int tid = threadIdx.x;
    const int img = blockIdx.x;
    const float* __restrict__ ip = out5 + (size_t)img * NN * 5;

    if (tid == 0) { s_cnt = 0; s_kw[0] = s_kw[1] = s_kw[2] = s_kw[3] = 0; }
    if (tid < KK * 4) ((unsigned*)s_sup)[tid] = 0;

    // targets early: DRAM latency overlaps the stream
    if (tid < KK) {
        const float* tp = tboxes + ((size_t)img * KK + tid) * 4;
        float t0 = fminf(fmaxf(__ldg(tp + 0), 0.0f), DS_);
        float t1 = fminf(fmaxf(__ldg(tp + 1), 0.0f), DS_);
        float t2 = fminf(fmaxf(__ldg(tp + 2), 0.0f), DS_);
        float t3 = fminf(fmaxf(__ldg(tp + 3), 0.0f), DS_);
        float tx1 = fminf(t0, t2), tx2 = fmaxf(t0, t2);
        float ty1 = fminf(t1, t3), ty2 = fmaxf(t1, t3);
        if (tx1 == tx2) tx2 = tx1 + 1.0f;
        if (ty1 == ty2) ty2 = ty1 + 1.0f;
        s_tx1[tid] = tx1; s_ty1[tid] = ty1; s_tx2[tid] = tx2; s_ty2[tid] = ty2;
    }
    __syncthreads();

    // ========== phase 1: stream whole image, candidates straight to smem ====
    #pragma unroll 6
    for (int e = tid; e < NN; e += THREADS) {
        float x = __ldg(&ip[(size_t)e * 5 + 4]);
        if (x > T0_) {
            int q = atomicAdd(&s_cnt, 1);
            if (q < CAP) {
                s_key[q] = make_cand(x, e);
                s_box[q] = build_box(ip, anchors, e);
            }
        }
    }
    __syncthreads();

    const int scnt = s_cnt;
    const bool fb = (scnt < KK || scnt > CAP);

    // ---- fallback: exact histogram top-K (never taken for typical inputs) ----
    if (fb) {
        for (int i = tid; i < NBUCK; i += THREADS) s_hist[i] = 0;
        if (tid == 0) s_cnt = 0;
        __syncthreads();
        for (int e = tid; e < NN; e += THREADS) {
            float x = ip[(size_t)e * 5 + 4];
            atomicAdd(&s_hist[fkey(x) >> 21], 1u);
        }
        __syncthreads();
        {
            unsigned s = 0;
            int base = (tid % 32) * (NBUCK / 32);      // warp 0 only below
            if (tid < 32) {
                #pragma unroll
                for (int j = 0; j < NBUCK / 32; j++) s += s_hist[base + j];
                s_fpart[tid] = s;
            }
        }
        __syncthreads();
        if (tid == 0) {
            unsigned cum = 0; int sg = 0;
            for (int t = 31; t >= 0; t--) {
                if (cum + s_fpart[t] >= KK) { sg = t; break; }
                cum += s_fpart[t];
            }
            int bsel = sg * (NBUCK / 32);
            for (int b = sg * (NBUCK / 32) + (NBUCK / 32) - 1;
                 b >= sg * (NBUCK / 32); b--) {
                cum += s_hist[b];
                if (cum >= KK) { bsel = b; break; }
            }
            s_bsel = bsel;
        }
        __syncthreads();
        const int bsel = s_bsel;
        for (int e = tid; e < NN; e += THREADS) {
            float x = ip[(size_t)e * 5 + 4];
            if ((int)(fkey(x) >> 21) >= bsel) {
                int pos = atomicAdd(&s_cnt, 1);
                if (pos < CAP) {
                    s_key[pos] = make_cand(x, e);
                    s_box[pos] = build_box(ip, anchors, e);
                }
            }
        }
        __syncthreads();
    }

    const int C = min(s_cnt, CAP);

    // ---- rank selection: exact top-K (keys unique) ----
    for (int c = tid; c < C; c += THREADS) {
        unsigned long long key = s_key[c];
        int rank = 0;
        #pragma unroll 8
        for (int j = 0; j < C; j++) rank += (s_key[j] > key) ? 1 : 0;
        if (rank < KK) {
            s_sele[rank] = c;
            s_selc[rank] = __uint_as_float((unsigned)(key >> 32) ^ 0x80000000u);
        }
    }
    __syncthreads();

    if (tid < KK) {
        float4 b = s_box[s_sele[tid]];
        s_bx1[tid] = b.x; s_by1[tid] = b.y; s_bx2[tid] = b.z; s_by2[tid] = b.w;
        s_ba[tid] = (b.z - b.x) * (b.w - b.y);
        if (s_selc[tid] >= 0.5f) atomicOr(&s_kw[tid >> 5], 1u << (tid & 31));
    }
    __syncthreads();

    // ---- pairwise pred-pred suppression bitmask (conditional atomics, rare) ----
    for (int q = tid; q < KK * KK; q += THREADS) {
        int i = q % KK, j = q / KK;
        if (j > i) {
            float lx = fmaxf(s_bx1[i], s_bx1[j]);
            float ly = fmaxf(s_by1[i], s_by1[j]);
            float rx = fminf(s_bx2[i], s_bx2[j]);
            float ry = fminf(s_by2[i], s_by2[j]);
            float iw = fmaxf(rx - lx, 0.0f), ih = fmaxf(ry - ly, 0.0f);
            float inter = iw * ih;
            float iou = __fdividef(inter, s_ba[i] + s_ba[j] - inter + EPS_);
            if (iou > 0.5f) atomicOr(&s_sup[i][j >> 5], 1u << (j & 31));
        }
    }
    __syncthreads();

    // ---- greedy NMS sweep (exact reference semantics), serial in thread 0 ----
    if (tid == 0) {
        const uint4* supv = (const uint4*)s_sup;
        unsigned kw0 = s_kw[0], kw1 = s_kw[1], kw2 = s_kw[2], kw3 = s_kw[3];
        #pragma unroll 4
        for (int i = 0; i < KK; i++) {
            uint4 r = supv[i];
            unsigned wv = (i < 32) ? kw0 : (i < 64) ? kw1 : (i < 96) ? kw2 : kw3;
            if ((wv >> (i & 31)) & 1u) {
                kw0 &= ~r.x; kw1 &= ~r.y; kw2 &= ~r.z; kw3 &= ~r.w;
            }
        }
        s_kw[0] = kw0; s_kw[1] = kw1; s_kw[2] = kw2; s_kw[3] = kw3;
    }
    __syncthreads();

    // ---- per-target max-IoU argmax: warp-owned targets, shuffle reduce ----
    {
        const int w = tid >> 5, l = tid & 31;
        unsigned kw[4] = { s_kw[0], s_kw[1], s_kw[2], s_kw[3] };
        for (int t = w; t < KK; t += THREADS / 32) {
            float tx1 = s_tx1[t], ty1 = s_ty1[t], tx2 = s_tx2[t], ty2 = s_ty2[t];
            float ta = (tx2 - tx1) * (ty2 - ty1);
            unsigned long long best = 0ull;
            #pragma unroll
            for (int p = l; p < KK + 28; p += 32) {
                if (p < KK) {
                    float kf = ((kw[p >> 5] >> (p & 31)) & 1u) ? 1.0f : 0.0f;
                    float lx = fmaxf(s_bx1[p], tx1);
                    float ly = fmaxf(s_by1[p], ty1);
                    float rx = fminf(s_bx2[p], tx2);
                    float ry = fminf(s_by2[p], ty2);
                    float iw = fmaxf(rx - lx, 0.0f), ih = fmaxf(ry - ly, 0.0f);
                    float inter = iw * ih;
                    float iou = __fdividef(inter, s_ba[p] + ta - inter + EPS_);
                    float v = iou * kf;
                    unsigned long long key =
                        ((unsigned long long)__float_as_uint(v) << 32)
                        | (unsigned)(0xFFFFFFFFu - (unsigned)p);
                    best = (key > best) ? key : best;
                }
            }
            #pragma unroll
            for (int off = 16; off; off >>= 1) {
                unsigned long long o = __shfl_down_sync(0xFFFFFFFFu, best, off);
                best = (o > best) ? o : best;
            }
            if (l == 0) s_best[t] = best;
        }
    }
    __syncthreads();

    // ---- per-target DIoU + penalty terms ----
    float diou = 0.0f, lowv = 0.0f, highv = 0.0f;
    if (tid < KK) {
        unsigned long long key = s_best[tid];
        float max_iou = fmaxf(__uint_as_float((unsigned)(key >> 32)), 0.0f);
        int best = (int)(0xFFFFFFFFu - (unsigned)(key & 0xFFFFFFFFull));
        float tx1 = s_tx1[tid], ty1 = s_ty1[tid], tx2 = s_tx2[tid], ty2 = s_ty2[tid];
        float pbx1 = s_bx1[best], pby1 = s_by1[best];
        float pbx2 = s_bx2[best], pby2 = s_by2[best];
        float pcx = (pbx1 + pbx2) * 0.5f, pcy = (pby1 + pby2) * 0.5f;
        float tcx = (tx1 + tx2) * 0.5f,  tcy = (ty1 + ty2) * 0.5f;
        float cd = (pcx - tcx) * (pcx - tcx) + (pcy - tcy) * (pcy - tcy);
        float ex1 = fminf(pbx1, tx1), ey1 = fminf(pby1, ty1);
        float ex2 = fmaxf(pbx2, tx2), ey2 = fmaxf(pby2, ty2);
        float dg = (ex2 - ex1) * (ex2 - ex1) + (ey2 - ey1) * (ey2 - ey1);
        diou = 1.0f - (max_iou - __fdividef(cd, dg + EPS_));

        float kfr = ((s_kw[tid >> 5] >> (tid & 31)) & 1u) ? 1.0f : 0.0f;
        float val = s_selc[tid];
        lowv  = fmaxf(-val, 0.0f) * kfr;
        highv = fmaxf(val - 1.0f, 0.0f) * kfr;
    }

    // deterministic reduction
    #pragma unroll
    for (int off = 16; off; off >>= 1) {
        diou  += __shfl_down_sync(0xFFFFFFFFu, diou,  off);
        lowv  += __shfl_down_sync(0xFFFFFFFFu, lowv,  off);
        highv += __shfl_down_sync(0xFFFFFFFFu, highv, off);
    }
    if ((tid & 31) == 0) {
        s_red[0][tid >> 5] = diou;
        s_red[1][tid >> 5] = lowv;
        s_red[2][tid >> 5] = highv;
    }
    __syncthreads();
    if (tid == 0) {
        float d = 0.0f, l = 0.0f, h = 0.0f;
        #pragma unroll
        for (int w = 0; w < 4; w++) {           // only warps 0-3 hold tid<KK data
            d += s_red[0][w]; l += s_red[1][w]; h += s_red[2][w];
        }
        float cnt = (float)(__popc(s_kw[0]) + __popc(s_kw[1]) +
                            __popc(s_kw[2]) + __popc(s_kw[3]));
        g_scratch[img * 4 + 0] = d;
        g_scratch[img * 4 + 1] = l;
        g_scratch[img * 4 + 2] = h;
        g_scratch[img * 4 + 3] = cnt;
        __threadfence();
        unsigned t = atomicAdd(&g_done, 1u);
        s_last = (t == BB - 1) ? 1 : 0;
    }
    __syncthreads();

    // ---- last CTA performs the global finalize ----
    if (s_last) {
        __threadfence();
        float d = 0.0f, l = 0.0f, h = 0.0f, c = 0.0f;
        if (tid < BB) {
            d = g_scratch[tid * 4 + 0];
            l = g_scratch[tid * 4 + 1];
            h = g_scratch[tid * 4 + 2];
            c = g_scratch[tid * 4 + 3];
        }
        #pragma unroll
        for (int off = 16; off; off >>= 1) {
            d += __shfl_down_sync(0xFFFFFFFFu, d, off);
            l += __shfl_down_sync(0xFFFFFFFFu, l, off);
            h += __shfl_down_sync(0xFFFFFFFFu, h, off);
            c += __shfl_down_sync(0xFFFFFFFFu, c, off);
        }
        if ((tid & 31) == 0) {
            s_red[0][tid >> 5] = d;
            s_red[1][tid >> 5] = l;
            s_red[2][tid >> 5] = h;
            s_cpart[tid >> 5]  = __float_as_uint(c);
        }
        __syncthreads();
        if (tid == 0) {
            float D = 0.0f, L = 0.0f, H = 0.0f, Cn = 0.0f;
            #pragma unroll
            for (int w = 0; w < 4; w++) {       // only warps 0-3 hold tid<BB data
                D += s_red[0][w]; L += s_red[1][w]; H += s_red[2][w];
                Cn += __uint_as_float(s_cpart[w]);
            }
            float n = fmaxf(Cn, 1.0f);
            out[0] = D / (float)(BB * KK) + L / n + 0.5f * (H / n);
            g_done = 0;                 // reset for next graph replay
        }
    }
}

extern "C" void kernel_launch(void* const* d_in, const int* in_sizes, int n_in,
                              void* d_out, int out_size)
{
    const float* output  = (const float*)d_in[0];   // (128,64,64,9,5) fp32
    const float* tboxes  = (const float*)d_in[1];   // (128,100,4) fp32
    const float* anchors = (const float*)d_in[2];   // (9,2) fp32
    float* out = (float*)d_out;

    fused_kernel<<<BB, THREADS>>>(output, tboxes, anchors, out);
}